// round 8
// baseline (speedup 1.0000x reference)
#include <cuda_runtime.h>
#include <cuda_bf16.h>
#include <cstdint>

#define NB     16
#define SEQ    512
#define DMODEL 512
#define MAXF   2048

// ---------------- scratch (static __device__ arrays: allowed) ----------------
__device__ __align__(128) __nv_bfloat16 g_Xhi[NB * MAXF * DMODEL];
__device__ __align__(128) __nv_bfloat16 g_Xlo[NB * MAXF * DMODEL];
__device__ __align__(128) __nv_bfloat16 g_Yhi[NB * MAXF * DMODEL];
__device__ __align__(128) __nv_bfloat16 g_Ylo[NB * MAXF * DMODEL];
__device__ __align__(128) __nv_bfloat16 g_Whi[6 * 3 * 512 * 512];   // [conv][tap][f][c]
__device__ __align__(128) __nv_bfloat16 g_Wlo[6 * 3 * 512 * 512];
__device__ float g_part[NB * MAXF * 4];
__device__ int   g_idx [NB * MAXF];

// ================= baseline-ISA helpers (compute_103-safe; NO tcgen05) =================
__device__ __forceinline__ uint32_t smem_to_u32(const void* p) {
    uint32_t a;
    asm("{ .reg .u64 t; cvta.to.shared.u64 t, %1; cvt.u32.u64 %0, t; }" : "=r"(a) : "l"(p));
    return a;
}
__device__ __forceinline__ void cpasync16(uint32_t dst, const void* src, bool pred) {
    int sz = pred ? 16 : 0;
    asm volatile("cp.async.cg.shared.global [%0], [%1], 16, %2;"
                 :: "r"(dst), "l"(src), "r"(sz));
}
#define CP_COMMIT() asm volatile("cp.async.commit_group;" ::: "memory")
#define CP_WAIT1()  asm volatile("cp.async.wait_group 1;"  ::: "memory")

__device__ __forceinline__ void ldmx4(uint32_t* r, uint32_t addr) {
    asm volatile("ldmatrix.sync.aligned.m8n8.x4.shared.b16 {%0,%1,%2,%3}, [%4];"
                 : "=r"(r[0]), "=r"(r[1]), "=r"(r[2]), "=r"(r[3]) : "r"(addr));
}
__device__ __forceinline__ void mma16816(float* d, const uint32_t* a, const uint32_t* b) {
    asm volatile("mma.sync.aligned.m16n8k16.row.col.f32.bf16.bf16.f32 "
                 "{%0,%1,%2,%3}, {%4,%5,%6,%7}, {%8,%9}, {%0,%1,%2,%3};"
                 : "+f"(d[0]), "+f"(d[1]), "+f"(d[2]), "+f"(d[3])
                 : "r"(a[0]), "r"(a[1]), "r"(a[2]), "r"(a[3]), "r"(b[0]), "r"(b[1]));
}
__device__ __forceinline__ uint32_t pack2bf(float a, float b) {
    __nv_bfloat162 t = __floats2bfloat162_rn(a, b);
    return *reinterpret_cast<uint32_t*>(&t);
}

// ---------------- weight transpose + hi/lo split: w[f][c][k] -> W*[conv][tap][f][c] ----------------
__global__ void wsplit_kernel(const float* __restrict__ w, int conv) {
    int tf  = blockIdx.x;            // 0..1535 = tap*512 + f
    int tap = tf >> 9;
    int f   = tf & 511;
    int c   = threadIdx.x;
    float v = w[(f * 512 + c) * 3 + tap];
    __nv_bfloat16 h = __float2bfloat16(v);
    float rem = v - __bfloat162float(h);
    long o = ((long)(conv * 3 + tap) * 512 + f) * 512 + c;
    g_Whi[o] = h;
    g_Wlo[o] = __float2bfloat16(rem);
}

// ---------------- split H (fp32) -> g_Xhi/g_Xlo ----------------
__global__ void hsplit_kernel(const float* __restrict__ H) {
    long i = (long)blockIdx.x * 512 + threadIdx.x * 4;
    float4 v = *(const float4*)&H[i];
    float vv[4] = {v.x, v.y, v.z, v.w};
    float hh[4];
#pragma unroll
    for (int k = 0; k < 4; k++) hh[k] = __bfloat162float(__float2bfloat16(vv[k]));
    *(uint32_t*)&g_Xhi[i]     = pack2bf(hh[0], hh[1]);
    *(uint32_t*)&g_Xhi[i + 2] = pack2bf(hh[2], hh[3]);
    *(uint32_t*)&g_Xlo[i]     = pack2bf(vv[0] - hh[0], vv[1] - hh[1]);
    *(uint32_t*)&g_Xlo[i + 2] = pack2bf(vv[2] - hh[2], vv[3] - hh[3]);
}

// ---------------- duration cumsum + searchsorted ----------------
__global__ void duration_idx_kernel(const int* __restrict__ Dgt) {
    __shared__ int cs[512];
    int b = blockIdx.x, tid = threadIdx.x;
    int v = Dgt[b * 512 + tid];
    cs[tid] = v > 0 ? v : 0;
    __syncthreads();
    for (int off = 1; off < 512; off <<= 1) {
        int add = (tid >= off) ? cs[tid - off] : 0;
        __syncthreads();
        cs[tid] += add;
        __syncthreads();
    }
    int total = cs[511];
    int Tmax  = total < MAXF ? total : MAXF;
    for (int t = tid; t < MAXF; t += 512) {
        int r;
        if (t >= Tmax) {
            r = -1;
        } else {
            int lo = 0, hi = 511;
            while (lo < hi) {
                int mid = (lo + hi) >> 1;
                if (cs[mid] > t) hi = mid; else lo = mid + 1;
            }
            r = lo;
        }
        g_idx[b * MAXF + t] = r;
    }
}

// ---------------- gather H_exp (split to g_X) + fused variance adapt ----------------
__global__ void gather_adapt_kernel(const float* __restrict__ H,
                                    const float* __restrict__ P,
                                    const float* __restrict__ E,
                                    const float* __restrict__ pw,
                                    const float* __restrict__ pb,
                                    const float* __restrict__ ew,
                                    const float* __restrict__ eb,
                                    float* __restrict__ outH) {
    int bt  = blockIdx.x;
    int b   = bt >> 11;
    int idx = g_idx[bt];
    int d   = threadIdx.x * 4;
    float4 h = make_float4(0.f, 0.f, 0.f, 0.f);
    if (idx >= 0) h = *(const float4*)&H[((long)(b * 512 + idx)) * 512 + d];

    long xo = (long)bt * 512 + d;
    float vv[4] = {h.x, h.y, h.z, h.w};
    float hh[4];
#pragma unroll
    for (int k = 0; k < 4; k++) hh[k] = __bfloat162float(__float2bfloat16(vv[k]));
    *(uint32_t*)&g_Xhi[xo]     = pack2bf(hh[0], hh[1]);
    *(uint32_t*)&g_Xhi[xo + 2] = pack2bf(hh[2], hh[3]);
    *(uint32_t*)&g_Xlo[xo]     = pack2bf(vv[0] - hh[0], vv[1] - hh[1]);
    *(uint32_t*)&g_Xlo[xo + 2] = pack2bf(vv[2] - hh[2], vv[3] - hh[3]);

    float p = P[bt], e = E[bt];
    float4 pw4 = *(const float4*)&pw[d];
    float4 pb4 = *(const float4*)&pb[d];
    float4 ew4 = *(const float4*)&ew[d];
    float4 eb4 = *(const float4*)&eb[d];
    float4 o;
    o.x = h.x + p * pw4.x + pb4.x + e * ew4.x + eb4.x;
    o.y = h.y + p * pw4.y + pb4.y + e * ew4.y + eb4.y;
    o.z = h.z + p * pw4.z + pb4.z + e * ew4.z + eb4.z;
    o.w = h.w + p * pw4.w + pb4.w + e * ew4.w + eb4.w;
    *(float4*)&outH[xo] = o;
}

// ---------------- tensor-core conv1d via mma.sync, 3xBF16 compensated ----------------
// CTA: 128 rows x 128 filters, 512 threads = 16 warps arranged 2(M)x4(N)x2(Ksplit).
// Warp tile 64x32, acc[4][4]; each warp covers 2 of the 4 k-slices per 64-ch chunk.
// A staged once per chunk (130 rows incl halo), taps via ldmatrix row offset.
// B triple-buffered ring (slot == tap), A double-buffered. One barrier / iteration.
// Epilogue: warpK=1 partials reduced into warpK=0 accs through smem.
#define A_BUF   33280      // hi+lo per A buffer
#define A_HALF  16640
#define B_BASE  66560
#define B_BUF   32768
#define B_HALF  16384
#define DSM_TOT (66560 + 98304)   // 164864

template <int FUSED>
__global__ __launch_bounds__(512, 1)
void conv_mma_kernel(int xsel, int conv, int S,
                     const float* __restrict__ bias, const float* __restrict__ wl) {
    extern __shared__ char sm[];
    const uint32_t sb = smem_to_u32(sm);
    __shared__ float s_bias[128];
    __shared__ float s_wl[128];
    __shared__ float s_part[128][4];

    const int tid  = threadIdx.x;
    const int lane = tid & 31;
    const int wid  = tid >> 5;
    const int warpM = wid & 1;          // 2 x 64 rows
    const int warpN = (wid >> 1) & 3;   // 4 x 32 cols
    const int warpK = wid >> 3;         // 2-way k-split
    const int rowW = warpM * 64, colW = warpN * 32;

    const int rowBase = blockIdx.y * 128;
    const int fBase   = blockIdx.x * 128;
    const int bb = rowBase / S;
    const int s0 = rowBase - bb * S;

    const __nv_bfloat16* Xhi = (xsel == 0 ? g_Xhi : g_Yhi) + (long)bb * S * 512;
    const __nv_bfloat16* Xlo = (xsel == 0 ? g_Xlo : g_Ylo) + (long)bb * S * 512;
    const __nv_bfloat16* WhC = g_Whi + ((long)(conv * 3) * 512 + fBase) * 512;
    const __nv_bfloat16* WlC = g_Wlo + ((long)(conv * 3) * 512 + fBase) * 512;

    if (tid < 128) {
        s_bias[tid] = bias[fBase + tid];
        if (FUSED) s_wl[tid] = wl[fBase + tid];
    }

    // ---- stage A chunk c: 130 rows x 64 ch (hi+lo) ----
    auto stageA = [&](int c) {
        const int c0 = c << 6;
        const uint32_t abuf = sb + (c & 1) * A_BUF;
#pragma unroll
        for (int q = 0; q < 3; q++) {
            int idx = tid + q * 512;
            if (idx < 1040) {                 // 130 rows x 8 segs
                int r = idx >> 3, c16 = idx & 7;
                int s = s0 - 1 + r;
                bool p = (s >= 0 && s < S);
                int sc = p ? s : 0;
                long off = (long)sc * 512 + c0 + c16 * 8;
                uint32_t dsw = (uint32_t)(r * 128 + ((c16 ^ (r & 7)) << 4));
                cpasync16(abuf + dsw,          Xhi + off, p);
                cpasync16(abuf + A_HALF + dsw, Xlo + off, p);
            }
        }
    };
    // ---- stage B for iteration it (chunk it/3, tap it%3) into ring slot it%3 ----
    auto stageB = [&](int it) {
        const int tap = it % 3;
        const int c0  = (it / 3) << 6;
        const uint32_t bbuf = sb + B_BASE + tap * B_BUF;
        const __nv_bfloat16* Wh = WhC + (long)tap * 512 * 512 + c0;
        const __nv_bfloat16* Wl = WlC + (long)tap * 512 * 512 + c0;
#pragma unroll
        for (int q = 0; q < 2; q++) {
            int idx = tid + q * 512;          // 0..1023: 128 filters x 8 segs
            int r = idx >> 3, c16 = idx & 7;
            long off = (long)r * 512 + c16 * 8;
            uint32_t dsw = (uint32_t)(r * 128 + ((c16 ^ (r & 7)) << 4));
            cpasync16(bbuf + dsw,          Wh + off, true);
            cpasync16(bbuf + B_HALF + dsw, Wl + off, true);
        }
    };

    // ---- per-lane ldmatrix bases ----
    const int q = lane >> 3;
    int am[4], an[2];
#pragma unroll
    for (int mt = 0; mt < 4; mt++) am[mt] = rowW + mt * 16 + ((q & 1) << 3) + (lane & 7);
#pragma unroll
    for (int np = 0; np < 2; np++) an[np] = colW + np * 16 + ((q >> 1) << 3) + (lane & 7);
    const int ac16b = q >> 1;
    const int bc16b = q & 1;

    float acc[4][4][4];
#pragma unroll
    for (int mt = 0; mt < 4; mt++)
#pragma unroll
        for (int nt = 0; nt < 4; nt++)
#pragma unroll
            for (int v = 0; v < 4; v++) acc[mt][nt][v] = 0.f;

    stageA(0); stageB(0); CP_COMMIT();        // group 0
    stageB(1);            CP_COMMIT();        // group 1

    for (int it = 0; it < 24; it++) {
        CP_WAIT1();                            // group 'it' complete
        __syncthreads();
        const int tap = it % 3;
        const uint32_t aH = sb + ((it / 3) & 1) * A_BUF;
        const uint32_t aL = aH + A_HALF;
        const uint32_t bH = sb + B_BASE + tap * B_BUF;
        const uint32_t bL = bH + B_HALF;

#pragma unroll
        for (int ksl = 0; ksl < 2; ksl++) {
            const int ks2 = (warpK * 2 + ksl) * 2;
            uint32_t bh[4][2], bl[4][2];
#pragma unroll
            for (int np = 0; np < 2; np++) {
                uint32_t off = (uint32_t)(an[np] * 128 + (((ks2 + bc16b) ^ (an[np] & 7)) << 4));
                uint32_t t[4];
                ldmx4(t, bH + off);
                bh[2 * np][0] = t[0]; bh[2 * np][1] = t[1];
                bh[2 * np + 1][0] = t[2]; bh[2 * np + 1][1] = t[3];
                ldmx4(t, bL + off);
                bl[2 * np][0] = t[0]; bl[2 * np][1] = t[1];
                bl[2 * np + 1][0] = t[2]; bl[2 * np + 1][1] = t[3];
            }
#pragma unroll
            for (int mt = 0; mt < 4; mt++) {
                const int pr = am[mt] + tap;
                uint32_t off = (uint32_t)(pr * 128 + (((ks2 + ac16b) ^ (pr & 7)) << 4));
                uint32_t ah[4], al[4];
                ldmx4(ah, aH + off);
                ldmx4(al, aL + off);
#pragma unroll
                for (int nt = 0; nt < 4; nt++) mma16816(acc[mt][nt], ah, bh[nt]);
#pragma unroll
                for (int nt = 0; nt < 4; nt++) mma16816(acc[mt][nt], ah, bl[nt]);
#pragma unroll
                for (int nt = 0; nt < 4; nt++) mma16816(acc[mt][nt], al, bh[nt]);
            }
        }

        const int nx = it + 2;
        if (nx < 24) {
            if (nx % 3 == 0) stageA(nx / 3);
            stageB(nx);
        }
        CP_COMMIT();
    }

    // ---------------- cross-warpK reduction through smem ----------------
    const int tq = lane >> 2;
    const int tr = lane & 3;
    float* spart = (float*)sm;                 // 128 x 132 fp32 (reuses A/B smem)
    __syncthreads();                           // all mainloop smem reads done
    if (warpK == 1) {
#pragma unroll
        for (int mt = 0; mt < 4; mt++)
#pragma unroll
            for (int nt = 0; nt < 4; nt++)
#pragma unroll
                for (int h = 0; h < 2; h++) {
                    int row = rowW + mt * 16 + tq + h * 8;
                    int col = colW + nt * 8 + 2 * tr;
                    *(float2*)&spart[row * 132 + col] =
                        make_float2(acc[mt][nt][2 * h], acc[mt][nt][2 * h + 1]);
                }
    }
    __syncthreads();

    if (warpK == 0) {
#pragma unroll
        for (int mt = 0; mt < 4; mt++)
#pragma unroll
            for (int nt = 0; nt < 4; nt++)
#pragma unroll
                for (int h = 0; h < 2; h++) {
                    int row = rowW + mt * 16 + tq + h * 8;
                    int col = colW + nt * 8 + 2 * tr;
                    float2 p = *(const float2*)&spart[row * 132 + col];
                    acc[mt][nt][2 * h]     += p.x;
                    acc[mt][nt][2 * h + 1] += p.y;
                }

        if (FUSED == 0) {
#pragma unroll
            for (int mt = 0; mt < 4; mt++) {
                const long r0 = rowBase + rowW + mt * 16 + tq;
#pragma unroll
                for (int nt = 0; nt < 4; nt++) {
                    const int cl = colW + nt * 8 + 2 * tr;
                    const float b0 = s_bias[cl], b1 = s_bias[cl + 1];
#pragma unroll
                    for (int h = 0; h < 2; h++) {
                        const long row = r0 + h * 8;
                        float v0 = fmaxf(acc[mt][nt][2 * h]     + b0, 0.f);
                        float v1 = fmaxf(acc[mt][nt][2 * h + 1] + b1, 0.f);
                        float h0 = __bfloat162float(__float2bfloat16(v0));
                        float h1 = __bfloat162float(__float2bfloat16(v1));
                        long o = row * 512 + fBase + cl;
                        *(uint32_t*)&g_Yhi[o] = pack2bf(h0, h1);
                        *(uint32_t*)&g_Ylo[o] = pack2bf(v0 - h0, v1 - h1);
                    }
                }
            }
        } else {
#pragma unroll
            for (int mt = 0; mt < 4; mt++) {
                float sum0 = 0.f, sum1 = 0.f;
#pragma unroll
                for (int nt = 0; nt < 4; nt++) {
                    const int cl = colW + nt * 8 + 2 * tr;
                    const float b0 = s_bias[cl], b1 = s_bias[cl + 1];
                    const float w0 = s_wl[cl], w1 = s_wl[cl + 1];
                    sum0 += fmaxf(acc[mt][nt][0] + b0, 0.f) * w0
                          + fmaxf(acc[mt][nt][1] + b1, 0.f) * w1;
                    sum1 += fmaxf(acc[mt][nt][2] + b0, 0.f) * w0
                          + fmaxf(acc[mt][nt][3] + b1, 0.f) * w1;
                }
                sum0 += __shfl_xor_sync(0xFFFFFFFF, sum0, 1);
                sum0 += __shfl_xor_sync(0xFFFFFFFF, sum0, 2);
                sum1 += __shfl_xor_sync(0xFFFFFFFF, sum1, 1);
                sum1 += __shfl_xor_sync(0xFFFFFFFF, sum1, 2);
                if (tr == 0) {
                    s_part[rowW + mt * 16 + tq][warpN]     = sum0;
                    s_part[rowW + mt * 16 + tq + 8][warpN] = sum1;
                }
            }
        }
    }
    if (FUSED == 1) {
        __syncthreads();
        if (tid < 128)
            g_part[(long)(rowBase + tid) * 4 + blockIdx.x] =
                (s_part[tid][0] + s_part[tid][1]) + (s_part[tid][2] + s_part[tid][3]);
    }
}

// ---------------- final pred reduce ----------------
__global__ void pred_reduce_kernel(const float* __restrict__ bl,
                                   float* __restrict__ out, int rows) {
    int i = blockIdx.x * 256 + threadIdx.x;
    if (i < rows)
        out[i] = bl[0] + g_part[(long)i * 4 + 0] + g_part[(long)i * 4 + 1] +
                 g_part[(long)i * 4 + 2] + g_part[(long)i * 4 + 3];
}

// ---------------- launch ----------------
extern "C" void kernel_launch(void* const* d_in, const int* in_sizes, int n_in,
                              void* d_out, int out_size) {
    const float* H     = (const float*)d_in[0];
    const int*   Dgt   = (const int*)  d_in[1];
    const float* Pgt   = (const float*)d_in[2];
    const float* Egt   = (const float*)d_in[3];
    const float* dp_w1 = (const float*)d_in[4];
    const float* dp_b1 = (const float*)d_in[5];
    const float* dp_w2 = (const float*)d_in[6];
    const float* dp_b2 = (const float*)d_in[7];
    const float* dp_wl = (const float*)d_in[8];
    const float* dp_bl = (const float*)d_in[9];
    const float* pp_w1 = (const float*)d_in[10];
    const float* pp_b1 = (const float*)d_in[11];
    const float* pp_w2 = (const float*)d_in[12];
    const float* pp_b2 = (const float*)d_in[13];
    const float* pp_wl = (const float*)d_in[14];
    const float* pp_bl = (const float*)d_in[15];
    const float* ep_w1 = (const float*)d_in[16];
    const float* ep_b1 = (const float*)d_in[17];
    const float* ep_w2 = (const float*)d_in[18];
    const float* ep_b2 = (const float*)d_in[19];
    const float* ep_wl = (const float*)d_in[20];
    const float* ep_bl = (const float*)d_in[21];
    const float* pw    = (const float*)d_in[22];
    const float* pb    = (const float*)d_in[23];
    const float* ew    = (const float*)d_in[24];
    const float* eb    = (const float*)d_in[25];

    float* out  = (float*)d_out;
    float* outH = out;                                   // (16,2048,512)
    float* outD = out + (long)NB * MAXF * DMODEL;        // (16,512)
    float* outP = outD + NB * SEQ;                       // (16,2048)
    float* outE = outP + NB * MAXF;                      // (16,2048)

    cudaFuncSetAttribute(conv_mma_kernel<0>, cudaFuncAttributeMaxDynamicSharedMemorySize, DSM_TOT);
    cudaFuncSetAttribute(conv_mma_kernel<1>, cudaFuncAttributeMaxDynamicSharedMemorySize, DSM_TOT);

    wsplit_kernel<<<1536, 512>>>(dp_w1, 0);
    wsplit_kernel<<<1536, 512>>>(dp_w2, 1);
    wsplit_kernel<<<1536, 512>>>(pp_w1, 2);
    wsplit_kernel<<<1536, 512>>>(pp_w2, 3);
    wsplit_kernel<<<1536, 512>>>(ep_w1, 4);
    wsplit_kernel<<<1536, 512>>>(ep_w2, 5);

    duration_idx_kernel<<<NB, 512>>>(Dgt);

    // ---- duration predictor (input: split H; S=512) ----
    hsplit_kernel<<<NB * SEQ, 128>>>(H);
    conv_mma_kernel<0><<<dim3(4, 64), 512, DSM_TOT>>>(0, 0, SEQ, dp_b1, nullptr);
    conv_mma_kernel<1><<<dim3(4, 64), 512, DSM_TOT>>>(1, 1, SEQ, dp_b2, dp_wl);
    pred_reduce_kernel<<<32, 256>>>(dp_bl, outD, NB * SEQ);

    // ---- expand + adapt (overwrites g_X with split Hexp; writes outH fp32) ----
    gather_adapt_kernel<<<NB * MAXF, 128>>>(H, Pgt, Egt, pw, pb, ew, eb, outH);

    // ---- pitch predictor (input: split Hexp; S=2048) ----
    conv_mma_kernel<0><<<dim3(4, 256), 512, DSM_TOT>>>(0, 2, MAXF, pp_b1, nullptr);
    conv_mma_kernel<1><<<dim3(4, 256), 512, DSM_TOT>>>(1, 3, MAXF, pp_b2, pp_wl);
    pred_reduce_kernel<<<128, 256>>>(pp_bl, outP, NB * MAXF);

    // ---- energy predictor (input: split Hexp, still in g_X; S=2048) ----
    conv_mma_kernel<0><<<dim3(4, 256), 512, DSM_TOT>>>(0, 4, MAXF, ep_b1, nullptr);
    conv_mma_kernel<1><<<dim3(4, 256), 512, DSM_TOT>>>(1, 5, MAXF, ep_b2, ep_wl);
    pred_reduce_kernel<<<128, 256>>>(ep_bl, outE, NB * MAXF);
}

// round 10
// speedup vs baseline: 1.0170x; 1.0170x over previous
#include <cuda_runtime.h>
#include <cuda_bf16.h>
#include <cstdint>

#define NB     16
#define SEQ    512
#define DMODEL 512
#define MAXF   2048

// ---------------- scratch (static __device__ arrays: allowed) ----------------
__device__ __align__(128) __nv_bfloat16 g_Xhi [NB * MAXF * DMODEL];  // Hexp split
__device__ __align__(128) __nv_bfloat16 g_Xlo [NB * MAXF * DMODEL];
__device__ __align__(128) __nv_bfloat16 g_Xdhi[NB * SEQ  * DMODEL];  // H split (dp input)
__device__ __align__(128) __nv_bfloat16 g_Xdlo[NB * SEQ  * DMODEL];
__device__ __align__(128) __nv_bfloat16 g_Yphi[NB * MAXF * DMODEL];  // pp layer1 out
__device__ __align__(128) __nv_bfloat16 g_Yplo[NB * MAXF * DMODEL];
__device__ __align__(128) __nv_bfloat16 g_Yehi[NB * MAXF * DMODEL];  // ep layer1 out
__device__ __align__(128) __nv_bfloat16 g_Yelo[NB * MAXF * DMODEL];
__device__ __align__(128) __nv_bfloat16 g_Ydhi[NB * SEQ  * DMODEL];  // dp layer1 out
__device__ __align__(128) __nv_bfloat16 g_Ydlo[NB * SEQ  * DMODEL];
__device__ __align__(128) __nv_bfloat16 g_Whi [6 * 3 * 512 * 512];   // [conv][tap][f][c]
__device__ __align__(128) __nv_bfloat16 g_Wlo [6 * 3 * 512 * 512];
#define TOTROWS (2 * NB * MAXF + NB * SEQ)   // pp | ep | dp row segments
__device__ float g_part[TOTROWS * 8];
__device__ int   g_idx [NB * MAXF];

// ================= baseline-ISA helpers (compute_103-safe; NO tcgen05) =================
__device__ __forceinline__ uint32_t smem_to_u32(const void* p) {
    uint32_t a;
    asm("{ .reg .u64 t; cvta.to.shared.u64 t, %1; cvt.u32.u64 %0, t; }" : "=r"(a) : "l"(p));
    return a;
}
__device__ __forceinline__ void cpasync16(uint32_t dst, const void* src, bool pred) {
    int sz = pred ? 16 : 0;
    asm volatile("cp.async.cg.shared.global [%0], [%1], 16, %2;"
                 :: "r"(dst), "l"(src), "r"(sz));
}
#define CP_COMMIT() asm volatile("cp.async.commit_group;" ::: "memory")
#define CP_WAIT1()  asm volatile("cp.async.wait_group 1;"  ::: "memory")

__device__ __forceinline__ void ldmx4(uint32_t* r, uint32_t addr) {
    asm volatile("ldmatrix.sync.aligned.m8n8.x4.shared.b16 {%0,%1,%2,%3}, [%4];"
                 : "=r"(r[0]), "=r"(r[1]), "=r"(r[2]), "=r"(r[3]) : "r"(addr));
}
__device__ __forceinline__ void mma16816(float* d, const uint32_t* a, const uint32_t* b) {
    asm volatile("mma.sync.aligned.m16n8k16.row.col.f32.bf16.bf16.f32 "
                 "{%0,%1,%2,%3}, {%4,%5,%6,%7}, {%8,%9}, {%0,%1,%2,%3};"
                 : "+f"(d[0]), "+f"(d[1]), "+f"(d[2]), "+f"(d[3])
                 : "r"(a[0]), "r"(a[1]), "r"(a[2]), "r"(a[3]), "r"(b[0]), "r"(b[1]));
}
__device__ __forceinline__ uint32_t pack2bf(float a, float b) {
    __nv_bfloat162 t = __floats2bfloat162_rn(a, b);
    return *reinterpret_cast<uint32_t*>(&t);
}

// smem tile address: 2 rows packed per 128B line, XOR swizzle. r = row, s = 16B seg (0..3)
__device__ __forceinline__ uint32_t tile_addr(int r, int s) {
    return (uint32_t)((r >> 1) * 128 + (((((r & 1) << 2) | s) ^ ((r >> 1) & 7)) << 4));
}

// ---------------- merged weight transpose + hi/lo split (all 6 convs) ----------------
__global__ void wsplit_all_kernel(const float* __restrict__ w0, const float* __restrict__ w1,
                                  const float* __restrict__ w2, const float* __restrict__ w3,
                                  const float* __restrict__ w4, const float* __restrict__ w5) {
    int conv = blockIdx.y;
    const float* w = conv == 0 ? w0 : conv == 1 ? w1 : conv == 2 ? w2 :
                     conv == 3 ? w3 : conv == 4 ? w4 : w5;
    int tf  = blockIdx.x;            // 0..1535 = tap*512 + f
    int tap = tf >> 9;
    int f   = tf & 511;
    int c   = threadIdx.x;
    float v = w[(f * 512 + c) * 3 + tap];
    __nv_bfloat16 h = __float2bfloat16(v);
    float rem = v - __bfloat162float(h);
    long o = ((long)(conv * 3 + tap) * 512 + f) * 512 + c;
    g_Whi[o] = h;
    g_Wlo[o] = __float2bfloat16(rem);
}

// ---------------- split H (fp32) -> g_Xdhi/g_Xdlo ----------------
__global__ void hsplit_kernel(const float* __restrict__ H) {
    long i = (long)blockIdx.x * 512 + threadIdx.x * 4;
    float4 v = *(const float4*)&H[i];
    float vv[4] = {v.x, v.y, v.z, v.w};
    float hh[4];
#pragma unroll
    for (int k = 0; k < 4; k++) hh[k] = __bfloat162float(__float2bfloat16(vv[k]));
    *(uint32_t*)&g_Xdhi[i]     = pack2bf(hh[0], hh[1]);
    *(uint32_t*)&g_Xdhi[i + 2] = pack2bf(hh[2], hh[3]);
    *(uint32_t*)&g_Xdlo[i]     = pack2bf(vv[0] - hh[0], vv[1] - hh[1]);
    *(uint32_t*)&g_Xdlo[i + 2] = pack2bf(vv[2] - hh[2], vv[3] - hh[3]);
}

// ---------------- duration cumsum + searchsorted ----------------
__global__ void duration_idx_kernel(const int* __restrict__ Dgt) {
    __shared__ int cs[512];
    int b = blockIdx.x, tid = threadIdx.x;
    int v = Dgt[b * 512 + tid];
    cs[tid] = v > 0 ? v : 0;
    __syncthreads();
    for (int off = 1; off < 512; off <<= 1) {
        int add = (tid >= off) ? cs[tid - off] : 0;
        __syncthreads();
        cs[tid] += add;
        __syncthreads();
    }
    int total = cs[511];
    int Tmax  = total < MAXF ? total : MAXF;
    for (int t = tid; t < MAXF; t += 512) {
        int r;
        if (t >= Tmax) {
            r = -1;
        } else {
            int lo = 0, hi = 511;
            while (lo < hi) {
                int mid = (lo + hi) >> 1;
                if (cs[mid] > t) hi = mid; else lo = mid + 1;
            }
            r = lo;
        }
        g_idx[b * MAXF + t] = r;
    }
}

// ---------------- gather H_exp (split to g_X) + fused variance adapt ----------------
__global__ void gather_adapt_kernel(const float* __restrict__ H,
                                    const float* __restrict__ P,
                                    const float* __restrict__ E,
                                    const float* __restrict__ pw,
                                    const float* __restrict__ pb,
                                    const float* __restrict__ ew,
                                    const float* __restrict__ eb,
                                    float* __restrict__ outH) {
    int bt  = blockIdx.x;
    int b   = bt >> 11;
    int idx = g_idx[bt];
    int d   = threadIdx.x * 4;
    float4 h = make_float4(0.f, 0.f, 0.f, 0.f);
    if (idx >= 0) h = *(const float4*)&H[((long)(b * 512 + idx)) * 512 + d];

    long xo = (long)bt * 512 + d;
    float vv[4] = {h.x, h.y, h.z, h.w};
    float hh[4];
#pragma unroll
    for (int k = 0; k < 4; k++) hh[k] = __bfloat162float(__float2bfloat16(vv[k]));
    *(uint32_t*)&g_Xhi[xo]     = pack2bf(hh[0], hh[1]);
    *(uint32_t*)&g_Xhi[xo + 2] = pack2bf(hh[2], hh[3]);
    *(uint32_t*)&g_Xlo[xo]     = pack2bf(vv[0] - hh[0], vv[1] - hh[1]);
    *(uint32_t*)&g_Xlo[xo + 2] = pack2bf(vv[2] - hh[2], vv[3] - hh[3]);

    float p = P[bt], e = E[bt];
    float4 pw4 = *(const float4*)&pw[d];
    float4 pb4 = *(const float4*)&pb[d];
    float4 ew4 = *(const float4*)&ew[d];
    float4 eb4 = *(const float4*)&eb[d];
    float4 o;
    o.x = h.x + p * pw4.x + pb4.x + e * ew4.x + eb4.x;
    o.y = h.y + p * pw4.y + pb4.y + e * ew4.y + eb4.y;
    o.z = h.z + p * pw4.z + pb4.z + e * ew4.z + eb4.z;
    o.w = h.w + p * pw4.w + pb4.w + e * ew4.w + eb4.w;
    *(float4*)&outH[xo] = o;
}

// noop: pads launch count so ncu -s 5 -c 1 captures the merged conv1 kernel
__global__ void noop_kernel() {}

// ---------------- merged tensor-core conv1d via mma.sync, 3xBF16 compensated ----------------
// One launch runs pp+ep+dp for a layer. Grid (8, 576): y<256 pp, <512 ep, else dp (64 blocks).
// CTA: 128 rows x 64 filters, 256 threads (8 warps 4Mx2N, warp 32x32), 32-ch K-chunks.
// 48 iterations = 16 chunks x 3 taps. A double-buffered per chunk (130-row halo shared by
// taps via ldmatrix row offset), B triple-buffered ring (slot == tap). Occupancy 2.
// LAYER=1: Y*hi/lo = split(relu(conv + bias)).  LAYER=2: g_part[row*8+xblk] = dot partials.
#define A_HALF  8320                 // 65 lines x 128B (130 rows, 32 ch bf16)
#define A_BUF   (2 * A_HALF)         // hi+lo
#define B_BASE  (2 * A_BUF)          // 33280
#define B_HALF  4096                 // 32 lines (64 filters, 32 ch)
#define B_SLOT  (2 * B_HALF)
#define DSM_TOT (B_BASE + 3 * B_SLOT)   // 57856

template <int LAYER>
__global__ __launch_bounds__(256, 2)
void conv_merged_kernel(const float* __restrict__ b_pp, const float* __restrict__ b_ep,
                        const float* __restrict__ b_dp, const float* __restrict__ wl_pp,
                        const float* __restrict__ wl_ep, const float* __restrict__ wl_dp) {
    extern __shared__ char sm[];
    const uint32_t sb = smem_to_u32(sm);
    __shared__ float s_bias[64];
    __shared__ float s_wl[64];
    __shared__ float s_part[128][2];

    const int tid  = threadIdx.x;
    const int lane = tid & 31;
    const int wid  = tid >> 5;
    const int warpM = wid & 3;          // 4 x 32 rows
    const int warpN = wid >> 2;         // 2 x 32 cols
    const int rowW = warpM * 32, colW = warpN * 32;

    // ---- job select ----
    const int y = blockIdx.y;
    int job, yl;
    if (y < 256)      { job = 0; yl = y; }
    else if (y < 512) { job = 1; yl = y - 256; }
    else              { job = 2; yl = y - 512; }
    const int S = (job == 2) ? SEQ : MAXF;
    const int conv = (LAYER == 1) ? (job == 0 ? 2 : job == 1 ? 4 : 0)
                                  : (job == 0 ? 3 : job == 1 ? 5 : 1);
    const float* bias = job == 0 ? b_pp : job == 1 ? b_ep : b_dp;
    const float* wl   = job == 0 ? wl_pp : job == 1 ? wl_ep : wl_dp;

    const __nv_bfloat16 *Xhi, *Xlo;
    __nv_bfloat16 *Ohi, *Olo;
    if (LAYER == 1) {
        Xhi = job == 2 ? g_Xdhi : g_Xhi;
        Xlo = job == 2 ? g_Xdlo : g_Xlo;
        Ohi = job == 0 ? g_Yphi : job == 1 ? g_Yehi : g_Ydhi;
        Olo = job == 0 ? g_Yplo : job == 1 ? g_Yelo : g_Ydlo;
    } else {
        Xhi = job == 0 ? g_Yphi : job == 1 ? g_Yehi : g_Ydhi;
        Xlo = job == 0 ? g_Yplo : job == 1 ? g_Yelo : g_Ydlo;
        Ohi = nullptr; Olo = nullptr;
    }
    const long rowOff = job == 0 ? 0 : job == 1 ? (long)NB * MAXF : 2L * NB * MAXF;

    const int rowBase = yl * 128;
    const int fBase   = blockIdx.x * 64;
    const int bb = rowBase / S;
    const int s0 = rowBase - bb * S;
    const __nv_bfloat16* Xbh = Xhi + (long)bb * S * 512;
    const __nv_bfloat16* Xbl = Xlo + (long)bb * S * 512;
    const __nv_bfloat16* WhC = g_Whi + ((long)(conv * 3) * 512 + fBase) * 512;
    const __nv_bfloat16* WlC = g_Wlo + ((long)(conv * 3) * 512 + fBase) * 512;

    if (tid < 64) {
        s_bias[tid] = bias[fBase + tid];
        if (LAYER == 2) s_wl[tid] = wl[fBase + tid];
    }

    // ---- stage A chunk c (32 ch, 130 rows incl halo, hi+lo) ----
    auto stageA = [&](int c) {
        const int c0 = c << 5;
        const uint32_t abuf = sb + (c & 1) * A_BUF;
#pragma unroll
        for (int q = 0; q < 3; q++) {
            int idx = tid + q * 256;
            if (idx < 520) {                  // 130 rows x 4 segs
                int r = idx >> 2, s = idx & 3;
                int sr = s0 - 1 + r;
                bool p = (sr >= 0 && sr < S);
                int sc = p ? sr : 0;
                long off = (long)sc * 512 + c0 + s * 8;
                uint32_t a = tile_addr(r, s);
                cpasync16(abuf + a,          Xbh + off, p);
                cpasync16(abuf + A_HALF + a, Xbl + off, p);
            }
        }
    };
    // ---- stage B for iteration it (chunk it/3, tap it%3) into slot it%3 ----
    auto stageB = [&](int it) {
        const int tap = it % 3;
        const int c0  = (it / 3) << 5;
        const uint32_t bbuf = sb + B_BASE + tap * B_SLOT;
        const __nv_bfloat16* Wh = WhC + (long)tap * 512 * 512 + c0;
        const __nv_bfloat16* Wl = WlC + (long)tap * 512 * 512 + c0;
        int r = tid >> 2, s = tid & 3;        // 64 filters x 4 segs = 256
        long off = (long)r * 512 + s * 8;
        uint32_t a = tile_addr(r, s);
        cpasync16(bbuf + a,          Wh + off, true);
        cpasync16(bbuf + B_HALF + a, Wl + off, true);
    };

    // ---- per-lane ldmatrix bases ----
    const int q = lane >> 3;
    int am[2], an[2];
#pragma unroll
    for (int mt = 0; mt < 2; mt++) am[mt] = rowW + mt * 16 + ((q & 1) << 3) + (lane & 7);
#pragma unroll
    for (int np = 0; np < 2; np++) an[np] = colW + np * 16 + ((q >> 1) << 3) + (lane & 7);
    const int ac16b = q >> 1;
    const int bc16b = q & 1;

    float acc[2][4][4];
#pragma unroll
    for (int mt = 0; mt < 2; mt++)
#pragma unroll
        for (int nt = 0; nt < 4; nt++)
#pragma unroll
            for (int v = 0; v < 4; v++) acc[mt][nt][v] = 0.f;

    stageA(0); stageB(0); CP_COMMIT();
    stageB(1);            CP_COMMIT();

    for (int it = 0; it < 48; it++) {
        CP_WAIT1();
        __syncthreads();
        const int tap = it % 3;
        const uint32_t aH = sb + ((it / 3) & 1) * A_BUF;
        const uint32_t aL = aH + A_HALF;
        const uint32_t bH = sb + B_BASE + tap * B_SLOT;
        const uint32_t bL = bH + B_HALF;

#pragma unroll
        for (int ksl = 0; ksl < 2; ksl++) {
            const int cA = ksl * 2 + ac16b;
            const int cB = ksl * 2 + bc16b;
            uint32_t bh[4][2], bl[4][2];
#pragma unroll
            for (int np = 0; np < 2; np++) {
                uint32_t off = (uint32_t)((an[np] >> 1) * 128 +
                    ((((an[np] & 1) << 2) | cB) ^ ((an[np] >> 1) & 7)) * 16);
                uint32_t t[4];
                ldmx4(t, bH + off);
                bh[2 * np][0] = t[0]; bh[2 * np][1] = t[1];
                bh[2 * np + 1][0] = t[2]; bh[2 * np + 1][1] = t[3];
                ldmx4(t, bL + off);
                bl[2 * np][0] = t[0]; bl[2 * np][1] = t[1];
                bl[2 * np + 1][0] = t[2]; bl[2 * np + 1][1] = t[3];
            }
#pragma unroll
            for (int mt = 0; mt < 2; mt++) {
                const int pr = am[mt] + tap;
                uint32_t off = (uint32_t)((pr >> 1) * 128 +
                    ((((pr & 1) << 2) | cA) ^ ((pr >> 1) & 7)) * 16);
                uint32_t ah[4], al[4];
                ldmx4(ah, aH + off);
                ldmx4(al, aL + off);
#pragma unroll
                for (int nt = 0; nt < 4; nt++) mma16816(acc[mt][nt], ah, bh[nt]);
#pragma unroll
                for (int nt = 0; nt < 4; nt++) mma16816(acc[mt][nt], ah, bl[nt]);
#pragma unroll
                for (int nt = 0; nt < 4; nt++) mma16816(acc[mt][nt], al, bh[nt]);
            }
        }

        const int nx = it + 2;
        if (nx < 48) {
            if (nx % 3 == 0) stageA(nx / 3);
            stageB(nx);
        }
        CP_COMMIT();
    }

    // ---------------- epilogue ----------------
    const int tq = lane >> 2;
    const int tr = lane & 3;
    if (LAYER == 1) {
#pragma unroll
        for (int mt = 0; mt < 2; mt++) {
            const long r0 = rowBase + rowW + mt * 16 + tq;
#pragma unroll
            for (int nt = 0; nt < 4; nt++) {
                const int cl = colW + nt * 8 + 2 * tr;
                const float b0 = s_bias[cl], b1 = s_bias[cl + 1];
#pragma unroll
                for (int h = 0; h < 2; h++) {
                    const long row = r0 + h * 8;
                    float v0 = fmaxf(acc[mt][nt][2 * h]     + b0, 0.f);
                    float v1 = fmaxf(acc[mt][nt][2 * h + 1] + b1, 0.f);
                    float h0 = __bfloat162float(__float2bfloat16(v0));
                    float h1 = __bfloat162float(__float2bfloat16(v1));
                    long o = row * 512 + fBase + cl;
                    *(uint32_t*)&Ohi[o] = pack2bf(h0, h1);
                    *(uint32_t*)&Olo[o] = pack2bf(v0 - h0, v1 - h1);
                }
            }
        }
    } else {
#pragma unroll
        for (int mt = 0; mt < 2; mt++) {
            float sum0 = 0.f, sum1 = 0.f;
#pragma unroll
            for (int nt = 0; nt < 4; nt++) {
                const int cl = colW + nt * 8 + 2 * tr;
                const float b0 = s_bias[cl], b1 = s_bias[cl + 1];
                const float w0 = s_wl[cl], w1 = s_wl[cl + 1];
                sum0 += fmaxf(acc[mt][nt][0] + b0, 0.f) * w0
                      + fmaxf(acc[mt][nt][1] + b1, 0.f) * w1;
                sum1 += fmaxf(acc[mt][nt][2] + b0, 0.f) * w0
                      + fmaxf(acc[mt][nt][3] + b1, 0.f) * w1;
            }
            sum0 += __shfl_xor_sync(0xFFFFFFFF, sum0, 1);
            sum0 += __shfl_xor_sync(0xFFFFFFFF, sum0, 2);
            sum1 += __shfl_xor_sync(0xFFFFFFFF, sum1, 1);
            sum1 += __shfl_xor_sync(0xFFFFFFFF, sum1, 2);
            if (tr == 0) {
                s_part[rowW + mt * 16 + tq][warpN]     = sum0;
                s_part[rowW + mt * 16 + tq + 8][warpN] = sum1;
            }
        }
        __syncthreads();
        if (tid < 128)
            g_part[(rowOff + rowBase + tid) * 8 + blockIdx.x] =
                s_part[tid][0] + s_part[tid][1];
    }
}

// ---------------- merged final reduce: pp | ep | dp ----------------
__global__ void reduce_all_kernel(const float* __restrict__ pp_bl,
                                  const float* __restrict__ ep_bl,
                                  const float* __restrict__ dp_bl,
                                  float* __restrict__ outP,
                                  float* __restrict__ outE,
                                  float* __restrict__ outD) {
    int i = blockIdx.x * 256 + threadIdx.x;
    if (i >= TOTROWS) return;
    float s = 0.f;
#pragma unroll
    for (int j = 0; j < 8; j++) s += g_part[(long)i * 8 + j];
    const int nPP = NB * MAXF, nPE = 2 * NB * MAXF;
    if (i < nPP)       outP[i]        = pp_bl[0] + s;
    else if (i < nPE)  outE[i - nPP]  = ep_bl[0] + s;
    else               outD[i - nPE]  = dp_bl[0] + s;
}

// ---------------- launch ----------------
extern "C" void kernel_launch(void* const* d_in, const int* in_sizes, int n_in,
                              void* d_out, int out_size) {
    const float* H     = (const float*)d_in[0];
    const int*   Dgt   = (const int*)  d_in[1];
    const float* Pgt   = (const float*)d_in[2];
    const float* Egt   = (const float*)d_in[3];
    const float* dp_w1 = (const float*)d_in[4];
    const float* dp_b1 = (const float*)d_in[5];
    const float* dp_w2 = (const float*)d_in[6];
    const float* dp_b2 = (const float*)d_in[7];
    const float* dp_wl = (const float*)d_in[8];
    const float* dp_bl = (const float*)d_in[9];
    const float* pp_w1 = (const float*)d_in[10];
    const float* pp_b1 = (const float*)d_in[11];
    const float* pp_w2 = (const float*)d_in[12];
    const float* pp_b2 = (const float*)d_in[13];
    const float* pp_wl = (const float*)d_in[14];
    const float* pp_bl = (const float*)d_in[15];
    const float* ep_w1 = (const float*)d_in[16];
    const float* ep_b1 = (const float*)d_in[17];
    const float* ep_w2 = (const float*)d_in[18];
    const float* ep_b2 = (const float*)d_in[19];
    const float* ep_wl = (const float*)d_in[20];
    const float* ep_bl = (const float*)d_in[21];
    const float* pw    = (const float*)d_in[22];
    const float* pb    = (const float*)d_in[23];
    const float* ew    = (const float*)d_in[24];
    const float* eb    = (const float*)d_in[25];

    float* out  = (float*)d_out;
    float* outH = out;                                   // (16,2048,512)
    float* outD = out + (long)NB * MAXF * DMODEL;        // (16,512)
    float* outP = outD + NB * SEQ;                       // (16,2048)
    float* outE = outP + NB * MAXF;                      // (16,2048)

    cudaFuncSetAttribute(conv_merged_kernel<1>, cudaFuncAttributeMaxDynamicSharedMemorySize, DSM_TOT);
    cudaFuncSetAttribute(conv_merged_kernel<2>, cudaFuncAttributeMaxDynamicSharedMemorySize, DSM_TOT);

    // 1: all weight splits
    wsplit_all_kernel<<<dim3(1536, 6), 512>>>(dp_w1, dp_w2, pp_w1, pp_w2, ep_w1, ep_w2);
    // 2: duration indices
    duration_idx_kernel<<<NB, 512>>>(Dgt);
    // 3: expand + adapt (writes split Hexp + outH)
    gather_adapt_kernel<<<NB * MAXF, 128>>>(H, Pgt, Egt, pw, pb, ew, eb, outH);
    // 4: split H for dp
    hsplit_kernel<<<NB * SEQ, 128>>>(H);
    // 5: pad so ncu (-s 5 -c 1) profiles the merged conv1
    noop_kernel<<<1, 32>>>();
    // 6: layer-1 convs (pp + ep + dp)
    conv_merged_kernel<1><<<dim3(8, 576), 256, DSM_TOT>>>(pp_b1, ep_b1, dp_b1,
                                                          nullptr, nullptr, nullptr);
    // 7: layer-2 convs + fused linear partials
    conv_merged_kernel<2><<<dim3(8, 576), 256, DSM_TOT>>>(pp_b2, ep_b2, dp_b2,
                                                          pp_wl, ep_wl, dp_wl);
    // 8: final reduce for all three predictors
    reduce_all_kernel<<<(TOTROWS + 255) / 256, 256>>>(pp_bl, ep_bl, dp_bl, outP, outE, outD);
}